// round 1
// baseline (speedup 1.0000x reference)
#include <cuda_runtime.h>
#include <cstdint>

#define BDIM 512
constexpr int Bn = 16, Nn = 2000, NP = 2048, Hh = 512, Ww = 512, MAXD = 10, TOPK_ = 5;
constexpr float CONF = 0.2f, IOUT = 0.4f;

// Scratch (device globals, allocation-free)
__device__ int g_bi[Bn][MAXD][4];
__device__ int g_k2[Bn][MAXD];

__device__ __forceinline__ float iou_f(float ax1, float ay1, float ax2, float ay2,
                                       float bx1, float by1, float bx2, float by2) {
    float aA = fmaxf(ax2 - ax1, 0.f) * fmaxf(ay2 - ay1, 0.f);
    float aB = fmaxf(bx2 - bx1, 0.f) * fmaxf(by2 - by1, 0.f);
    float ix1 = fmaxf(ax1, bx1), iy1 = fmaxf(ay1, by1);
    float ix2 = fminf(ax2, bx2), iy2 = fminf(ay2, by2);
    float it = fmaxf(ix2 - ix1, 0.f) * fmaxf(iy2 - iy1, 0.f);
    return it / (aA + aB - it + 1e-9f);
}

extern __shared__ unsigned char dynsmem[];

__global__ __launch_bounds__(BDIM) void nms_kernel(const float* __restrict__ region,
                                                   const float* __restrict__ neg,
                                                   float* __restrict__ out_tb,
                                                   float* __restrict__ out_k2) {
    unsigned long long* skey = (unsigned long long*)dynsmem;      // NP keys (16KB)
    float4* sbox = (float4*)(dynsmem + NP * 8);                    // NP boxes (32KB)
    __shared__ unsigned long long alive[NP / 64];
    __shared__ int outlist[MAXD];
    __shared__ int sh_cur, sh_found, sh_done;

    const int t = threadIdx.x;
    const int b = blockIdx.x;
    const float* rb = region + (size_t)b * Nn * 5;

    // ---- build sort keys: (score_bits << 32) | (N-1-idx) for stable desc order ----
    for (int j = t; j < NP; j += BDIM) {
        unsigned long long key = 0ull;
        if (j < Nn) {
            float sc = rb[j * 5 + 4];
            key = ((unsigned long long)__float_as_uint(sc) << 32) | (unsigned)(Nn - 1 - j);
        }
        skey[j] = key;
    }

    // ---- bitonic sort, descending ----
    for (int k = 2; k <= NP; k <<= 1) {
        for (int j = k >> 1; j > 0; j >>= 1) {
            __syncthreads();
            for (int i = t; i < NP; i += BDIM) {
                int l = i ^ j;
                if (l > i) {
                    unsigned long long a = skey[i], c = skey[l];
                    bool up = ((i & k) == 0);
                    if (up ? (a < c) : (a > c)) { skey[i] = c; skey[l] = a; }
                }
            }
        }
    }
    __syncthreads();

    // ---- gather boxes in sorted order ----
    for (int s = t; s < NP; s += BDIM) {
        int j = (Nn - 1) - (int)(unsigned)(skey[s] & 0xffffffffu);
        const float* p = rb + j * 5;
        sbox[s] = make_float4(p[0], p[1], p[2], p[3]);
    }
    if (t == 0) { sh_cur = -1; sh_found = 0; sh_done = 0; }
    __syncthreads();

    float topsc = __uint_as_float((unsigned)(skey[0] >> 32));
    bool has_conf = topsc > CONF;                 // any score > CONF (max is rank 0)
    float thresh = has_conf ? CONF : 0.0f;
    int limit = has_conf ? MAXD : TOPK_;

    // alive bitmask init: valid = score > thresh (sorted => prefix, but compute generally)
    if (t < NP / 64) {
        unsigned long long w = 0ull;
        for (int bb = 0; bb < 64; ++bb) {
            float sc = __uint_as_float((unsigned)(skey[t * 64 + bb] >> 32));
            if (sc > thresh) w |= (1ull << bb);
        }
        alive[t] = w;
    }

    // ---- greedy NMS with early exit once `limit` tiny-kept boxes found ----
    for (;;) {
        __syncthreads();
        if (t < 32) {
            int cur = sh_cur;
            unsigned long long mm = alive[t];
            int base = t * 64;
            if (cur >= base + 63) mm = 0ull;
            else if (cur >= base) mm &= ~((1ull << (cur - base + 1)) - 1ull);
            unsigned bal = __ballot_sync(0xffffffffu, mm != 0ull);
            if (bal) {
                int lw = __ffs(bal) - 1;
                unsigned long long wsel = __shfl_sync(0xffffffffu, mm, lw);
                int s = lw * 64 + __ffsll((long long)wsel) - 1;
                if (t == 0) {
                    sh_cur = s;
                    float4 bx = sbox[s];
                    if ((bx.z - bx.x >= 1.0f) && (bx.w - bx.y >= 1.0f)) {
                        outlist[sh_found] = s;
                        sh_found = sh_found + 1;
                        if (sh_found == limit) sh_done = 1;
                    }
                }
            } else if (t == 0) {
                sh_done = 1;
            }
        }
        __syncthreads();
        if (sh_done) break;
        int s = sh_cur;
        float4 bi = sbox[s];
#pragma unroll
        for (int p = 0; p < NP / BDIM; p++) {
            int r = t + p * BDIM;
            if (r > s) {
                int w = r >> 6;
                unsigned long long bm = 1ull << (r & 63);
                if (alive[w] & bm) {
                    float4 bj = sbox[r];
                    float io = iou_f(bi.x, bi.y, bi.z, bi.w, bj.x, bj.y, bj.z, bj.w);
                    if (io > IOUT) atomicAnd(&alive[w], ~bm);
                }
            }
        }
    }

    // ---- stage 2: 10-box merge + sort + NMS + outputs (single thread, trivial) ----
    if (t == 0) {
        int cnt = sh_found;   // == min(count, limit) exactly
        float cb[MAXD][5];
        for (int k = 0; k < MAXD; k++) {
            if (k < cnt) {
                int s = outlist[k];
                float4 bx = sbox[s];
                cb[k][0] = bx.x; cb[k][1] = bx.y; cb[k][2] = bx.z; cb[k][3] = bx.w;
                cb[k][4] = __uint_as_float((unsigned)(skey[s] >> 32));
            } else {
                const float* p = neg + (size_t)b * MAXD * 5 + k * 5;
                for (int c = 0; c < 5; c++) cb[k][c] = p[c];
            }
        }
        // stable insertion sort, descending by conf
        for (int i = 1; i < MAXD; i++) {
            float tmp[5];
            for (int c = 0; c < 5; c++) tmp[c] = cb[i][c];
            int j = i - 1;
            while (j >= 0 && cb[j][4] < tmp[4]) {
                for (int c = 0; c < 5; c++) cb[j + 1][c] = cb[j][c];
                j--;
            }
            for (int c = 0; c < 5; c++) cb[j + 1][c] = tmp[c];
        }
        // 10x10 greedy NMS, valid = conf > 0
        bool k2[MAXD];
        for (int i = 0; i < MAXD; i++) k2[i] = cb[i][4] > 0.0f;
        for (int i = 0; i < MAXD; i++) {
            if (!k2[i]) continue;
            for (int jn = i + 1; jn < MAXD; jn++) {
                float io = iou_f(cb[i][0], cb[i][1], cb[i][2], cb[i][3],
                                 cb[jn][0], cb[jn][1], cb[jn][2], cb[jn][3]);
                if (io > IOUT) k2[jn] = false;
            }
        }
        for (int k = 0; k < MAXD; k++) {
            bool kk = k2[k];
            for (int c = 0; c < 4; c++) {
                out_tb[(size_t)b * MAXD * 4 + k * 4 + c] = kk ? cb[k][c] : 0.0f;
                g_bi[b][k][c] = (int)floorf(cb[k][c] + 0.5f);
            }
            out_k2[(size_t)b * MAXD + k] = kk ? 1.0f : 0.0f;
            g_k2[b][k] = kk ? 1 : 0;
        }
    }
}

// One block per (row, image); each thread writes 4 pixels as float4.
__global__ __launch_bounds__(128) void render_kernel(float* __restrict__ out) {
    int b = blockIdx.y;
    int y = blockIdx.x;
    __shared__ int sx1[MAXD], sy1[MAXD], sx2[MAXD], sy2[MAXD], sk[MAXD];
    int t = threadIdx.x;
    if (t < MAXD) {
        sk[t] = g_k2[b][t];
        sx1[t] = g_bi[b][t][0];
        sy1[t] = g_bi[b][t][1];
        sx2[t] = g_bi[b][t][2];
        sy2[t] = g_bi[b][t][3];
    }
    __syncthreads();
    int xb = t * 4;
    float v0 = 1.f, v1 = 1.f, v2 = 1.f, v3 = 1.f;
#pragma unroll
    for (int k = 0; k < MAXD; k++) {
        if (sk[k] && y >= sy1[k] && y < sy2[k]) {
            int a = sx1[k], c = sx2[k];
            if (xb >= a && xb < c) v0 = 0.f;
            if (xb + 1 >= a && xb + 1 < c) v1 = 0.f;
            if (xb + 2 >= a && xb + 2 < c) v2 = 0.f;
            if (xb + 3 >= a && xb + 3 < c) v3 = 0.f;
        }
    }
    *(float4*)(out + ((size_t)b * Hh + y) * Ww + xb) = make_float4(v0, v1, v2, v3);
}

extern "C" void kernel_launch(void* const* d_in, const int* in_sizes, int n_in,
                              void* d_out, int out_size) {
    // inputs: [0]=x (unused), [1]=region_boxes (B,N,5), [2]=neg_boxes (B,10,5)
    const float* region = (const float*)d_in[1];
    const float* neg = (const float*)d_in[2];
    float* out = (float*)d_out;
    float* out_tb = out + (size_t)Bn * Hh * Ww;          // target_boxes segment
    float* out_k2 = out_tb + (size_t)Bn * MAXD * 4;      // keep2 segment

    const int smem_bytes = NP * 8 + NP * 16;             // 49152 B
    cudaFuncSetAttribute(nms_kernel, cudaFuncAttributeMaxDynamicSharedMemorySize, smem_bytes);
    nms_kernel<<<Bn, BDIM, smem_bytes>>>(region, neg, out_tb, out_k2);
    render_kernel<<<dim3(Hh, Bn), 128>>>(out);
}

// round 2
// speedup vs baseline: 1.7625x; 1.7625x over previous
#include <cuda_runtime.h>
#include <cstdint>
#include <climits>

#define BDIM 512
constexpr int Bn = 16, Nn = 2000, NP = 2048, Hh = 512, Ww = 512, MAXD = 10, TOPK_ = 5;
constexpr float CONF = 0.2f, IOUT = 0.4f;

// Scratch (device globals, allocation-free)
__device__ int g_bi[Bn][MAXD][4];
__device__ int g_k2[Bn][MAXD];

__device__ __forceinline__ float iou_f(float ax1, float ay1, float ax2, float ay2,
                                       float bx1, float by1, float bx2, float by2) {
    float aA = fmaxf(ax2 - ax1, 0.f) * fmaxf(ay2 - ay1, 0.f);
    float aB = fmaxf(bx2 - bx1, 0.f) * fmaxf(by2 - by1, 0.f);
    float ix1 = fmaxf(ax1, bx1), iy1 = fmaxf(ay1, by1);
    float ix2 = fminf(ax2, bx2), iy2 = fminf(ay2, by2);
    float it = fmaxf(ix2 - ix1, 0.f) * fmaxf(iy2 - iy1, 0.f);
    return it / (aA + aB - it + 1e-9f);
}

extern __shared__ unsigned char dynsmem[];

// dynamic smem layout
//   allkey : ULL[NP]     @ 0
//   ckey   : ULL[NP]     @ 16384
//   skeys  : ULL[NP]     @ 32768
//   sboxs  : float4[NP]  @ 49152
// total 81920 B
__global__ __launch_bounds__(BDIM) void nms_kernel(const float* __restrict__ region,
                                                   const float* __restrict__ neg,
                                                   float* __restrict__ out_tb,
                                                   float* __restrict__ out_k2) {
    unsigned long long* allkey = (unsigned long long*)dynsmem;
    unsigned long long* ckey   = (unsigned long long*)(dynsmem + 16384);
    unsigned long long* skeys  = (unsigned long long*)(dynsmem + 32768);
    float4*             sboxs  = (float4*)(dynsmem + 49152);

    __shared__ int hist[256];
    __shared__ unsigned int sh_maxbits;
    __shared__ int sh_binthr, sh_total, sh_cnt, sh_C, sh_found;
    __shared__ int outlist[MAXD];

    const int t = threadIdx.x;
    const int b = blockIdx.x;
    const int lane = t & 31;
    const float* rb = region + (size_t)b * Nn * 5;

    if (t == 0) sh_maxbits = 0u;
    for (int h = t; h < 256; h += BDIM) hist[h] = 0;
    __syncthreads();

    // ---- load keys (score<<32 | Nn-1-idx), block max score ----
    unsigned int localmax = 0u;
    for (int j = t; j < NP; j += BDIM) {
        unsigned long long key = 0ull;
        if (j < Nn) {
            float sc = rb[j * 5 + 4];
            unsigned int sb = __float_as_uint(sc);
            key = ((unsigned long long)sb << 32) | (unsigned)(Nn - 1 - j);
            if (sb > localmax) localmax = sb;   // scores > 0 -> uint order == float order
        }
        allkey[j] = key;
    }
#pragma unroll
    for (int off = 16; off; off >>= 1)
        localmax = max(localmax, __shfl_xor_sync(0xffffffffu, localmax, off));
    if (lane == 0) atomicMax(&sh_maxbits, localmax);
    __syncthreads();

    const bool has_conf = __uint_as_float(sh_maxbits) > CONF;
    const float thresh = has_conf ? CONF : 0.0f;
    const int limit = has_conf ? MAXD : TOPK_;

    // ---- histogram of valid scores ----
    for (int j = t; j < NP; j += BDIM) {
        float sc = __uint_as_float((unsigned)(allkey[j] >> 32));
        if (sc > thresh) {
            int bin = (int)(sc * 256.0f);
            bin = min(max(bin, 0), 255);
            atomicAdd(&hist[bin], 1);
        }
    }
    __syncthreads();

    // ---- candidate selection with escalation fallback ----
    for (int TARGET = 64;; TARGET <<= 2) {
        if (t == 0) {
            int cum = 0, binthr = 0;
            bool got = false;
            for (int bb = 255; bb >= 0; bb--) {
                cum += hist[bb];
                if (!got && cum >= TARGET) { binthr = bb; got = true; }
            }
            sh_binthr = got ? binthr : 0;
            sh_total = cum;
            sh_cnt = 0;
        }
        __syncthreads();
        const int binthr = sh_binthr;

        // compact candidate keys
        for (int j = t; j < NP; j += BDIM) {
            unsigned long long key = allkey[j];
            float sc = __uint_as_float((unsigned)(key >> 32));
            if (sc > thresh) {
                int bin = min(max((int)(sc * 256.0f), 0), 255);
                if (bin >= binthr) {
                    int pos = atomicAdd(&sh_cnt, 1);
                    ckey[pos] = key;
                }
            }
        }
        __syncthreads();
        const int C = sh_cnt;
        if (t == 0) sh_C = C;

        // rank sort (descending by key; keys unique -> exact stable order)
        for (int i = t; i < C; i += BDIM) {
            unsigned long long ki = ckey[i];
            int rank = 0;
            for (int j = 0; j < C; j++) rank += (ckey[j] > ki);
            skeys[rank] = ki;
        }
        __syncthreads();
        // gather boxes for sorted candidates
        for (int s = t; s < C; s += BDIM) {
            int j = (Nn - 1) - (int)(unsigned)(skeys[s] & 0xffffffffu);
            const float* p = rb + j * 5;
            sboxs[s] = make_float4(p[0], p[1], p[2], p[3]);
        }
        __syncthreads();

        // ---- single-warp greedy NMS with early exit ----
        if (t < 32) {
            unsigned long long aliveb = 0ull;
            for (int bs = 0; bs < 64; bs++)
                if (bs * 32 + lane < C) aliveb |= (1ull << bs);
            int found = 0;
            for (;;) {
                int myidx = aliveb ? ((__ffsll((long long)aliveb) - 1) * 32 + lane) : INT_MAX;
#pragma unroll
                for (int off = 16; off; off >>= 1)
                    myidx = min(myidx, __shfl_xor_sync(0xffffffffu, myidx, off));
                if (myidx == INT_MAX) break;
                int s = myidx;
                float4 bi = sboxs[s];
                if ((s & 31) == lane) aliveb &= ~(1ull << (s >> 5));
                if ((bi.z - bi.x >= 1.0f) && (bi.w - bi.y >= 1.0f)) {
                    if (lane == 0) outlist[found] = s;
                    found++;
                    if (found == limit) break;
                }
                // suppress remaining alive (all have idx > s now)
                unsigned long long mm = aliveb;
                while (mm) {
                    int b0 = __ffsll((long long)mm) - 1;
                    mm &= mm - 1;
                    int idx = b0 * 32 + lane;
                    float4 bj = sboxs[idx];
                    if (iou_f(bi.x, bi.y, bi.z, bi.w, bj.x, bj.y, bj.z, bj.w) > IOUT)
                        aliveb &= ~(1ull << b0);
                }
            }
            if (lane == 0) sh_found = found;
        }
        __syncthreads();

        if (sh_found >= limit || sh_C >= sh_total || TARGET >= NP) break;
        __syncthreads();
    }

    // ---- stage 2: 10-box merge + sort + NMS + outputs (single thread) ----
    if (t == 0) {
        int cnt = min(sh_found, limit);
        float cb[MAXD][5];
        for (int k = 0; k < MAXD; k++) {
            if (k < cnt) {
                int s = outlist[k];
                float4 bx = sboxs[s];
                cb[k][0] = bx.x; cb[k][1] = bx.y; cb[k][2] = bx.z; cb[k][3] = bx.w;
                cb[k][4] = __uint_as_float((unsigned)(skeys[s] >> 32));
            } else {
                const float* p = neg + (size_t)b * MAXD * 5 + k * 5;
                for (int c = 0; c < 5; c++) cb[k][c] = p[c];
            }
        }
        // stable insertion sort, descending by conf
        for (int i = 1; i < MAXD; i++) {
            float tmp[5];
            for (int c = 0; c < 5; c++) tmp[c] = cb[i][c];
            int j = i - 1;
            while (j >= 0 && cb[j][4] < tmp[4]) {
                for (int c = 0; c < 5; c++) cb[j + 1][c] = cb[j][c];
                j--;
            }
            for (int c = 0; c < 5; c++) cb[j + 1][c] = tmp[c];
        }
        // 10x10 greedy NMS, valid = conf > 0
        bool k2[MAXD];
        for (int i = 0; i < MAXD; i++) k2[i] = cb[i][4] > 0.0f;
        for (int i = 0; i < MAXD; i++) {
            if (!k2[i]) continue;
            for (int jn = i + 1; jn < MAXD; jn++) {
                float io = iou_f(cb[i][0], cb[i][1], cb[i][2], cb[i][3],
                                 cb[jn][0], cb[jn][1], cb[jn][2], cb[jn][3]);
                if (io > IOUT) k2[jn] = false;
            }
        }
        for (int k = 0; k < MAXD; k++) {
            bool kk = k2[k];
            for (int c = 0; c < 4; c++) {
                out_tb[(size_t)b * MAXD * 4 + k * 4 + c] = kk ? cb[k][c] : 0.0f;
                g_bi[b][k][c] = (int)floorf(cb[k][c] + 0.5f);
            }
            out_k2[(size_t)b * MAXD + k] = kk ? 1.0f : 0.0f;
            g_k2[b][k] = kk ? 1 : 0;
        }
    }
}

// streaming fill of 1.0f over the whole mask region
__global__ __launch_bounds__(256) void fill_kernel(float4* __restrict__ out) {
    size_t i = (size_t)blockIdx.x * blockDim.x + threadIdx.x;
    out[i] = make_float4(1.f, 1.f, 1.f, 1.f);
}

// zero out covered pixels; one block per (image, slot)
__global__ __launch_bounds__(256) void boxzero_kernel(float* __restrict__ out) {
    int b = blockIdx.x / MAXD, k = blockIdx.x % MAXD;
    if (!g_k2[b][k]) return;
    int x1 = max(g_bi[b][k][0], 0), y1 = max(g_bi[b][k][1], 0);
    int x2 = min(g_bi[b][k][2], Ww), y2 = min(g_bi[b][k][3], Hh);
    int w = x2 - x1, h = y2 - y1;
    if (w <= 0 || h <= 0) return;
    int area = w * h;
    float* base = out + (size_t)b * Hh * Ww;
    for (int i = threadIdx.x; i < area; i += blockDim.x) {
        int y = y1 + i / w, x = x1 + i % w;
        base[y * Ww + x] = 0.0f;
    }
}

extern "C" void kernel_launch(void* const* d_in, const int* in_sizes, int n_in,
                              void* d_out, int out_size) {
    // inputs: [0]=x (unused), [1]=region_boxes (B,N,5), [2]=neg_boxes (B,10,5)
    const float* region = (const float*)d_in[1];
    const float* neg = (const float*)d_in[2];
    float* out = (float*)d_out;
    float* out_tb = out + (size_t)Bn * Hh * Ww;          // target_boxes segment
    float* out_k2 = out_tb + (size_t)Bn * MAXD * 4;      // keep2 segment

    const int smem_bytes = 81920;
    cudaFuncSetAttribute(nms_kernel, cudaFuncAttributeMaxDynamicSharedMemorySize, smem_bytes);

    const int total4 = Bn * Hh * Ww / 4;                 // 1M float4
    fill_kernel<<<total4 / 256, 256>>>((float4*)out);
    nms_kernel<<<Bn, BDIM, smem_bytes>>>(region, neg, out_tb, out_k2);
    boxzero_kernel<<<Bn * MAXD, 256>>>(out);
}